// round 6
// baseline (speedup 1.0000x reference)
#include <cuda_runtime.h>
#include <cuda_bf16.h>

// MatchSegmentation, single fused kernel.
//   ce[k,g] = -( C_k + sum_{n: gi[g,n]=1} d[k,n] ) / N,  d = log(s+e)-log(1-s+e)
//   argmin_g ce == argmax_g D[k,g]  (positive scale ok -> log2, drop constants)
//
// Inputs identified by size signature; seg vs gt disambiguated on-device by
// bit pattern (gt int words are 0/1). Output = float32 indices.
//
// R5 (resubmitted after infra timeout): contiguous smem layout (no
// per-element division), balanced tiles (wall = 2 tiles/block), uint4 mask
// loads in phase 2, fused reduction.

#define EPS 1e-6f
#define T_CAP 536
#define KREF 21
#define SD_FLOATS (KREF * T_CAP)      // 11256 floats = 45024 B
#define MAXGRID 304
#define MAXPAIR 1024
#define GMAX 32

__device__ float g_part[MAXPAIR * MAXGRID];
__device__ unsigned g_cnt = 0;

__global__ __launch_bounds__(512, 2) void ms_fused_kernel(
    const void* __restrict__ Av, const void* __restrict__ Bv,
    const int* __restrict__ gpn, float* __restrict__ out,
    int out_size, int N, int K, int P, int T, int grid, int nprobe)
{
    __shared__ float sd[SD_FLOATS];            // sd[t*K + k] (contiguous)
    __shared__ unsigned smask[T_CAP];
    __shared__ int s_tmp[2];
    __shared__ int s_cfg[2];                   // [0]=asel, [1]=G
    __shared__ float s_D[KREF * GMAX];
    __shared__ unsigned s_done;

    const int j = threadIdx.x;

    // ---- per-block parallel probe: which big input is segmentation? ----
    if (j < 64) {
        int i = j & 31;
        int idx = (i < nprobe) ? i : 0;
        unsigned w = (j < 32) ? ((const unsigned*)Av)[idx]
                              : ((const unsigned*)Bv)[idx];
        unsigned bal = __ballot_sync(0xffffffffu, w > 1u);
        if ((j & 31) == 0) s_tmp[j >> 5] = __popc(bal);
    }
    __syncthreads();
    if (j == 0) {
        s_cfg[0] = (s_tmp[0] >= s_tmp[1]) ? 1 : 0;   // 1 -> A is seg
        int G = gpn ? *gpn : 20;
        if (G < 1 || G > 1000000) G = 20;
        if (G > GMAX) G = GMAX;
        if (G > P) G = P;
        if (G < 1) G = 1;
        s_cfg[1] = G;
    }
    __syncthreads();

    const int asel = s_cfg[0];
    const float* __restrict__ seg = asel ? (const float*)Av : (const float*)Bv;
    const int*   __restrict__ gt  = asel ? (const int*)Bv  : (const int*)Av;
    const int G = s_cfg[1];
    int NPAIR = K * G;
    if (NPAIR > MAXPAIR) NPAIR = MAXPAIR;

    // ---- pair ownership (up to 2 pairs per thread; NPAIR <= 672) ----
    int k0 = -1, k1 = -1;
    unsigned b0 = 0, b1 = 0;
    if (j < NPAIR)       { k0 = j / G;         b0 = 1u << (j % G); }
    if (j + 512 < NPAIR) { k1 = (j + 512) / G; b1 = 1u << ((j + 512) % G); }
    float acc0 = 0.0f, acc1 = 0.0f;

    const int ntiles = (N + T - 1) / T;

    for (int tile = blockIdx.x; tile < ntiles; tile += gridDim.x) {
        const int base = tile * T;
        const int nt = min(T, N - base);

        // ---- Phase 1a: per-pixel GT bit masks ----
        if (((nt & 3) == 0) && ((base & 3) == 0) && ((N & 3) == 0)) {
            int nq = nt >> 2;
            for (int q = j; q < nq; q += 512) {
                unsigned m0 = 0, m1 = 0, m2 = 0, m3 = 0;
                const int* gp = gt + base + 4 * q;
                for (int g = 0; g < G; g++) {
                    int4 v = *(const int4*)(gp + (size_t)g * N);
                    unsigned bit = 1u << g;
                    if (v.x) m0 |= bit;
                    if (v.y) m1 |= bit;
                    if (v.z) m2 |= bit;
                    if (v.w) m3 |= bit;
                }
                smask[4 * q + 0] = m0;
                smask[4 * q + 1] = m1;
                smask[4 * q + 2] = m2;
                smask[4 * q + 3] = m3;
            }
        } else {
            for (int t = j; t < nt; t += 512) {
                unsigned m = 0;
                for (int g = 0; g < G; g++)
                    if (gt[(size_t)g * N + base + t]) m |= 1u << g;
                smask[t] = m;
            }
        }

        // ---- Phase 1b: d = log2(s+e)-log2(1-s+e), contiguous sd[t*K+k] ----
        const int nelem = nt * K;
        const size_t off = (size_t)base * (size_t)K;
        if (((off & 3) == 0) && ((nelem & 3) == 0)) {
            const float4* sv = (const float4*)(seg + off);
            int n4 = nelem >> 2;
            for (int q = j; q < n4; q += 512) {
                float4 s = sv[q];
                float d0 = __log2f(s.x + EPS) - __log2f(1.0f - s.x + EPS);
                float d1 = __log2f(s.y + EPS) - __log2f(1.0f - s.y + EPS);
                float d2 = __log2f(s.z + EPS) - __log2f(1.0f - s.z + EPS);
                float d3 = __log2f(s.w + EPS) - __log2f(1.0f - s.w + EPS);
                *(float4*)&sd[4 * q] = make_float4(d0, d1, d2, d3);
            }
        } else {
            for (int e = j; e < nelem; e += 512) {
                float s = seg[off + e];
                sd[e] = __log2f(s + EPS) - __log2f(1.0f - s + EPS);
            }
        }
        __syncthreads();

        // ---- Phase 2: sweep tile; uint4 mask + scalar dv (broadcast LDS) ----
        const int nt4 = nt & ~3;
        if (k0 >= 0) {
            float a0 = 0.0f, a1 = 0.0f;
            for (int t = 0; t < nt4; t += 4) {
                uint4 m = *(const uint4*)(smask + t);
                const float* p = sd + t * K + k0;
                float d0 = p[0];
                float d1 = p[K];
                float d2 = p[2 * K];
                float d3 = p[3 * K];
                if (m.x & b0) a0 += d0;
                if (m.y & b0) a1 += d1;
                if (m.z & b0) a0 += d2;
                if (m.w & b0) a1 += d3;
            }
            for (int t = nt4; t < nt; t++)
                if (smask[t] & b0) a0 += sd[t * K + k0];
            acc0 += a0 + a1;
        }
        if (k1 >= 0) {
            float a0 = 0.0f, a1 = 0.0f;
            for (int t = 0; t < nt4; t += 4) {
                uint4 m = *(const uint4*)(smask + t);
                const float* p = sd + t * K + k1;
                float d0 = p[0];
                float d1 = p[K];
                float d2 = p[2 * K];
                float d3 = p[3 * K];
                if (m.x & b1) a0 += d0;
                if (m.y & b1) a1 += d1;
                if (m.z & b1) a0 += d2;
                if (m.w & b1) a1 += d3;
            }
            for (int t = nt4; t < nt; t++)
                if (smask[t] & b1) a0 += sd[t * K + k1];
            acc1 += a0 + a1;
        }
        __syncthreads();
    }

    // ---- write per-block partials (pure writes; no zeroing needed) ----
    const int blk = blockIdx.x;
    if (k0 >= 0) g_part[j * MAXGRID + blk] = acc0;
    if (k1 >= 0) g_part[(j + 512) * MAXGRID + blk] = acc1;

    // ---- last-block reduction + argmax ----
    __threadfence();
    if (j == 0) s_done = atomicAdd(&g_cnt, 1u);
    __syncthreads();
    if (s_done == (unsigned)(grid - 1)) {
        for (int p = j; p < NPAIR; p += 512) {
            float sum = 0.0f;
            const float* row = &g_part[p * MAXGRID];
            for (int b = 0; b < grid; b++)
                sum += __ldcg(row + b);        // L2 read: bypass stale L1
            int kk = p / G, gg = p - kk * G;
            if (kk < KREF) s_D[kk * GMAX + gg] = sum;
        }
        __syncthreads();
        for (int k = j; k < out_size; k += 512) {
            if (k < K && k < KREF) {
                float best = s_D[k * GMAX];
                int bi = 0;
                for (int g = 1; g < G; g++) {
                    float v = s_D[k * GMAX + g];
                    if (v > best) { best = v; bi = g; }  // first-max tie rule
                }
                out[k] = (float)bi;
            } else {
                out[k] = 0.0f;
            }
        }
        if (j == 0) g_cnt = 0;                 // reset for next graph replay
    }
}

extern "C" void kernel_launch(void* const* d_in, const int* in_sizes, int n_in,
                              void* d_out, int out_size)
{
    // ---- identify inputs by size signature (ordering-invariant) ----
    int imax = 0;
    for (int i = 1; i < n_in; i++)
        if (in_sizes[i] > in_sizes[imax]) imax = i;
    int jmax = -1;
    for (int i = 0; i < n_in; i++)
        if (i != imax && in_sizes[i] == in_sizes[imax]) { jmax = i; break; }
    if (jmax < 0) {
        imax = 0;
        jmax = (n_in > 2) ? 2 : (n_in > 1 ? 1 : 0);
    }

    int N = 1;
    int gpn_idx = -1;
    for (int i = 0; i < n_in; i++) {
        if (i == imax || i == jmax) continue;
        if (in_sizes[i] > N) N = in_sizes[i];
        if (in_sizes[i] == 1) gpn_idx = i;
    }
    if (N < 1) N = 1;
    long long M = in_sizes[imax];
    int K = (int)(M / N);
    if (K < 1) K = 1;
    if (K > KREF) K = KREF;     // fixed-shape problem; smem sized for K<=21

    const int* gpn = (gpn_idx >= 0) ? (const int*)d_in[gpn_idx] : nullptr;

    // ---- balanced tiling: wall <= 2 tiles per block ----
    const int GRID0 = 296;                      // 2 blocks x 148 SMs
    int T = (N + 2 * GRID0 - 1) / (2 * GRID0);  // ceil(N / (2*grid))
    T = (T + 3) & ~3;                           // multiple of 4
    if (T < 4) T = 4;
    int tcap = (SD_FLOATS / K) & ~3;            // smem capacity bound
    if (tcap > T_CAP) tcap = T_CAP;
    if (T > tcap) T = tcap;

    int ntiles = (N + T - 1) / T;
    int grid = ntiles < GRID0 ? ntiles : GRID0;
    if (grid > MAXGRID) grid = MAXGRID;
    if (grid < 1) grid = 1;

    int nprobe = (int)(M < 32 ? M : 32);
    if (nprobe < 1) nprobe = 1;

    ms_fused_kernel<<<grid, 512>>>(d_in[imax], d_in[jmax], gpn,
                                   (float*)d_out, out_size,
                                   N, K, KREF, T, grid, nprobe);
}

// round 9
// speedup vs baseline: 1.7004x; 1.7004x over previous
#include <cuda_runtime.h>

// MatchSegmentation, single fused kernel.
//   ce[k,g] = -( C_k + sum_{n: gi[g,n]=1} d[k,n] ) / N,  d = log(s+e)-log(1-s+e)
//   argmin_g ce == argmax_g D[k,g]  (positive scale ok -> log2, drop constants)
//
// R7 (third submission; two infra timeouts): NO min-blocks launch_bounds
// clamp (R4/R6's forced 64-reg cap is the suspected 2x regression). Spec
// path for K=21,G=20: coalesced unrolled phase-1a, immediate-offset
// phase-2. atomicAdd tail into g_D + self-reset.

#define EPS 1e-6f
#define KS 21
#define GS 20
#define NPS (KS * GS)                  // 420
#define T_CAP 536
#define SD_FLOATS (KS * T_CAP)         // 11256 floats
#define GMAX 32
#define NPMAX 1024

__device__ float g_D[NPMAX];           // zero-init at load; tail re-zeros
__device__ unsigned g_cnt = 0;

__global__ __launch_bounds__(512) void ms_kernel(
    const void* __restrict__ Av, const void* __restrict__ Bv,
    const int* __restrict__ gpn, float* __restrict__ out,
    int out_size, int N, int K, int T, int grid, int nprobe)
{
    __shared__ float sd[SD_FLOATS];    // sd[t*K + k], contiguous
    __shared__ unsigned smask[T_CAP];
    __shared__ int s_tmp[2];
    __shared__ int s_cfg[2];           // [0]=asel, [1]=G
    __shared__ unsigned s_rank;

    const int j = threadIdx.x;

    // ---- per-block probe: which big input is segmentation? ----
    if (j < 64) {
        int i = j & 31;
        int idx = (i < nprobe) ? i : 0;
        unsigned w = (j < 32) ? ((const unsigned*)Av)[idx]
                              : ((const unsigned*)Bv)[idx];
        unsigned bal = __ballot_sync(0xffffffffu, w > 1u);
        if ((j & 31) == 0) s_tmp[j >> 5] = __popc(bal);
    }
    __syncthreads();
    if (j == 0) {
        s_cfg[0] = (s_tmp[0] >= s_tmp[1]) ? 1 : 0;   // 1 -> A is seg
        int G = gpn ? *gpn : 20;
        if (G < 1 || G > 1000000) G = 20;
        if (G > GMAX) G = GMAX;
        if (G > K) G = K;          // gt planes stored = K rows
        if (G < 1) G = 1;
        s_cfg[1] = G;
    }
    __syncthreads();

    const int asel = s_cfg[0];
    const float* __restrict__ seg = asel ? (const float*)Av : (const float*)Bv;
    const int*   __restrict__ gt  = asel ? (const int*)Bv  : (const int*)Av;
    const int G = s_cfg[1];
    int NPAIR = K * G;
    if (NPAIR > NPMAX) NPAIR = NPMAX;

    const int ntiles = (N + T - 1) / T;
    const bool spec = (K == KS) && (G == GS);

    if (spec) {
        // ================= specialized path: K=21, G=20 =================
        const int k0 = j / GS;                  // valid for j < 420
        const unsigned b0 = 1u << (j - k0 * GS);
        float acc = 0.0f;

        for (int tile = blockIdx.x; tile < ntiles; tile += gridDim.x) {
            const int base = tile * T;
            const int nt = min(T, N - base);

            // ---- Phase 1a: coalesced scalar loads, unrolled G=20 ----
            for (int t = j; t < nt; t += 512) {
                const int* gp = gt + base + t;
                unsigned m = 0;
                #pragma unroll
                for (int g = 0; g < GS; g++)
                    if (gp[(size_t)g * N]) m |= (1u << g);
                smask[t] = m;
            }

            // ---- Phase 1b: d = log2(s+e)-log2(1-s+e) into sd[t*21+k] ----
            const int nelem = nt * KS;
            const size_t off = (size_t)base * KS;
            if (((off & 3) == 0) && ((nelem & 3) == 0)) {
                const float4* sv = (const float4*)(seg + off);
                const int n4 = nelem >> 2;
                for (int q = j; q < n4; q += 512) {
                    float4 s = sv[q];
                    float d0 = __log2f(s.x + EPS) - __log2f(1.0f - s.x + EPS);
                    float d1 = __log2f(s.y + EPS) - __log2f(1.0f - s.y + EPS);
                    float d2 = __log2f(s.z + EPS) - __log2f(1.0f - s.z + EPS);
                    float d3 = __log2f(s.w + EPS) - __log2f(1.0f - s.w + EPS);
                    *(float4*)&sd[4 * q] = make_float4(d0, d1, d2, d3);
                }
            } else {
                for (int e = j; e < nelem; e += 512) {
                    float s = seg[off + e];
                    sd[e] = __log2f(s + EPS) - __log2f(1.0f - s + EPS);
                }
            }
            __syncthreads();

            // ---- Phase 2: per-pair sweep, compile-time strides ----
            if (j < NPS) {
                const float* sdk = sd + k0;
                float a0 = 0.0f, a1 = 0.0f;
                const int nt4 = nt & ~3;
                for (int t = 0; t < nt4; t += 4) {
                    uint4 m = *(const uint4*)(smask + t);
                    float d0 = sdk[t * KS];
                    float d1 = sdk[t * KS + KS];
                    float d2 = sdk[t * KS + 2 * KS];
                    float d3 = sdk[t * KS + 3 * KS];
                    if (m.x & b0) a0 += d0;
                    if (m.y & b0) a1 += d1;
                    if (m.z & b0) a0 += d2;
                    if (m.w & b0) a1 += d3;
                }
                for (int t = nt4; t < nt; t++)
                    if (smask[t] & b0) a0 += sdk[t * KS];
                acc += a0 + a1;
            }
            __syncthreads();
        }

        if (j < NPS) atomicAdd(&g_D[j], acc);
    } else {
        // ================= generic path =================
        int k0 = -1, k1 = -1;
        unsigned b0 = 0, b1 = 0;
        if (j < NPAIR)       { k0 = j / G;         b0 = 1u << (j % G); }
        if (j + 512 < NPAIR) { k1 = (j + 512) / G; b1 = 1u << ((j + 512) % G); }
        float acc0 = 0.0f, acc1 = 0.0f;

        for (int tile = blockIdx.x; tile < ntiles; tile += gridDim.x) {
            const int base = tile * T;
            const int nt = min(T, N - base);

            for (int t = j; t < nt; t += 512) {
                unsigned m = 0;
                for (int g = 0; g < G; g++)
                    if (gt[(size_t)g * N + base + t]) m |= 1u << g;
                smask[t] = m;
            }
            const int nelem = nt * K;
            const size_t off = (size_t)base * (size_t)K;
            for (int e = j; e < nelem; e += 512) {
                float s = seg[off + e];
                sd[e] = __log2f(s + EPS) - __log2f(1.0f - s + EPS);
            }
            __syncthreads();

            if (k0 >= 0) {
                float a = 0.0f;
                for (int t = 0; t < nt; t++)
                    if (smask[t] & b0) a += sd[t * K + k0];
                acc0 += a;
            }
            if (k1 >= 0) {
                float a = 0.0f;
                for (int t = 0; t < nt; t++)
                    if (smask[t] & b1) a += sd[t * K + k1];
                acc1 += a;
            }
            __syncthreads();
        }
        if (k0 >= 0) atomicAdd(&g_D[j], acc0);
        if (k1 >= 0) atomicAdd(&g_D[j + 512], acc1);
    }

    // ---- last-block tail: argmax + output + reset ----
    __threadfence();
    if (j == 0) s_rank = atomicAdd(&g_cnt, 1u);
    __syncthreads();
    if (s_rank == (unsigned)(grid - 1)) {
        for (int p = j; p < NPAIR; p += 512) sd[p] = __ldcg(&g_D[p]);
        __syncthreads();
        for (int k = j; k < out_size; k += 512) {
            if (k < K) {
                float best = sd[k * G];
                int bi = 0;
                for (int g = 1; g < G; g++) {
                    float v = sd[k * G + g];
                    if (v > best) { best = v; bi = g; }  // first-max tie rule
                }
                out[k] = (float)bi;
            } else {
                out[k] = 0.0f;
            }
        }
        for (int p = j; p < NPAIR; p += 512) g_D[p] = 0.0f;  // reset for replay
        if (j == 0) g_cnt = 0;
    }
}

extern "C" void kernel_launch(void* const* d_in, const int* in_sizes, int n_in,
                              void* d_out, int out_size)
{
    // ---- identify inputs by size signature (ordering-invariant) ----
    int imax = 0;
    for (int i = 1; i < n_in; i++)
        if (in_sizes[i] > in_sizes[imax]) imax = i;
    int jmax = -1;
    for (int i = 0; i < n_in; i++)
        if (i != imax && in_sizes[i] == in_sizes[imax]) { jmax = i; break; }
    if (jmax < 0) {
        imax = 0;
        jmax = (n_in > 2) ? 2 : (n_in > 1 ? 1 : 0);
    }

    int N = 1;
    int gpn_idx = -1;
    for (int i = 0; i < n_in; i++) {
        if (i == imax || i == jmax) continue;
        if (in_sizes[i] > N) N = in_sizes[i];
        if (in_sizes[i] == 1) gpn_idx = i;
    }
    if (N < 1) N = 1;
    long long M = in_sizes[imax];
    int K = (int)(M / N);
    if (K < 1) K = 1;
    if (K > KS) K = KS;     // fixed-shape problem; smem sized for K<=21

    const int* gpn = (gpn_idx >= 0) ? (const int*)d_in[gpn_idx] : nullptr;

    // ---- balanced tiling: wall <= 2 tiles per block ----
    const int GRID0 = 296;                      // 2 blocks x 148 SMs
    int T = (N + 2 * GRID0 - 1) / (2 * GRID0);  // ceil(N / (2*grid))
    T = (T + 3) & ~3;
    if (T < 4) T = 4;
    int tcap = (SD_FLOATS / K) & ~3;
    if (tcap > T_CAP) tcap = T_CAP;
    if (T > tcap) T = tcap;

    int ntiles = (N + T - 1) / T;
    int grid = ntiles < GRID0 ? ntiles : GRID0;
    if (grid < 1) grid = 1;

    int nprobe = (int)(M < 32 ? M : 32);
    if (nprobe < 1) nprobe = 1;

    ms_kernel<<<grid, 512>>>(d_in[imax], d_in[jmax], gpn,
                             (float*)d_out, out_size,
                             N, K, T, grid, nprobe);
}

// round 11
// speedup vs baseline: 2.3201x; 1.3644x over previous
#include <cuda_runtime.h>

// MatchSegmentation, single fused kernel.
//   ce[k,g] = -( C_k + sum_n d[k,n]*gi[g,n] ) / N,  d = log(s+e)-log(1-s+e)
//   argmin_g ce == argmax_g D[k,g]  (positive scale ok -> log2, drop consts)
//
// R10 (resubmitted after infra timeout): phase 2 is a pure FFMA micro-GEMM:
// D[k,g] += d[k,t]*mf[g,t] with mf = float(gt) rows in smem (exactly the
// reference's gi GEMM operand). sd transposed [k][t] (compile-time K=21 ->
// magic div), LDS.128 loads, 16 FFMA / 4 px / thread, no per-pixel
// predicates. T=288, 47.9KB static smem -> 4 blocks/SM, grid 592.
// Block-level reduce then 4 atomics/output.

#define EPS 1e-6f
#define KS 21
#define GS 20
#define NPS (KS * GS)              // 420
#define T_SPEC 288
#define TPAD 292                   // mult of 4; TPAD/4=73 odd -> bank spread
#define SEG 72                     // T_SPEC/4, multiple of 4
#define SD_FLOATS (KS * TPAD)      // 6132
#define MF_FLOATS (GS * TPAD)      // 5840
#define SM_FLOATS (SD_FLOATS + MF_FLOATS)  // 11972 floats = 47888 B
#define GRID_SPEC 592
#define GMAX 32
#define NPMAX 1024

__device__ float g_D[NPMAX];       // zero-init at load; tail re-zeros
__device__ unsigned g_cnt = 0;

__global__ __launch_bounds__(512) void ms_kernel(
    const void* __restrict__ Av, const void* __restrict__ Bv,
    const int* __restrict__ gpn, float* __restrict__ out,
    int out_size, int N, int K, int T, int grid, int nprobe)
{
    __shared__ float smem[SM_FLOATS];
    __shared__ int s_tmp[2];
    __shared__ int s_cfg[2];       // [0]=asel, [1]=G
    __shared__ unsigned s_rank;

    float* const sd = smem;                    // spec: sd[k*TPAD + t]
    float* const mf = smem + SD_FLOATS;        // spec: mf[g*TPAD + t]

    const int j = threadIdx.x;

    // ---- per-block probe: which big input is segmentation? ----
    if (j < 64) {
        int i = j & 31;
        int idx = (i < nprobe) ? i : 0;
        unsigned w = (j < 32) ? ((const unsigned*)Av)[idx]
                              : ((const unsigned*)Bv)[idx];
        unsigned bal = __ballot_sync(0xffffffffu, w > 1u);
        if ((j & 31) == 0) s_tmp[j >> 5] = __popc(bal);
    }
    __syncthreads();
    if (j == 0) {
        s_cfg[0] = (s_tmp[0] >= s_tmp[1]) ? 1 : 0;   // 1 -> A is seg
        int G = gpn ? *gpn : 20;
        if (G < 1 || G > 1000000) G = 20;
        if (G > GMAX) G = GMAX;
        if (G > K) G = K;
        if (G < 1) G = 1;
        s_cfg[1] = G;
    }
    __syncthreads();

    const int asel = s_cfg[0];
    const float* __restrict__ seg = asel ? (const float*)Av : (const float*)Bv;
    const int*   __restrict__ gt  = asel ? (const int*)Bv  : (const int*)Av;
    const int G = s_cfg[1];
    int NPAIR = K * G;
    if (NPAIR > NPMAX) NPAIR = NPMAX;

    const int ntiles = (N + T - 1) / T;
    const bool spec = (K == KS) && (G == GS) && ((N & 3) == 0) && (T == T_SPEC);

    if (spec) {
        // ================= specialized path: K=21, G=20 =================
        // thread (tid<420): s = tid/105; k = (tid%105)/5; gq = tid%5
        // owns outputs D[k][gq + 5i], i=0..3, over pixel segment s.
        const int sidx = j / 105;
        const int rem = j - sidx * 105;
        const int kk = rem / 5;
        const int gq = rem - kk * 5;
        const bool act = (j < NPS);
        float a0 = 0.f, a1 = 0.f, a2 = 0.f, a3 = 0.f;

        for (int tile = blockIdx.x; tile < ntiles; tile += gridDim.x) {
            const int base = tile * T_SPEC;
            const int nt = min(T_SPEC, N - base);   // multiple of 4

            // ---- Phase 1a: expand GT ints to float rows mf[g][t] ----
            for (int t = j; t < nt; t += 512) {
                const int* gp = gt + base + t;
                #pragma unroll
                for (int g = 0; g < GS; g++)
                    mf[g * TPAD + t] = (float)gp[(size_t)g * N];
            }

            // ---- Phase 1b: d = log2(s+e)-log2(1-s+e) into sd[k][t] ----
            {
                const float4* sv = (const float4*)(seg + (size_t)base * KS);
                const int n4 = (nt * KS) >> 2;
                for (int q = j; q < n4; q += 512) {
                    float4 s4 = sv[q];
                    const int e = 4 * q;
                    float d0 = __log2f(s4.x + EPS) - __log2f(1.0f - s4.x + EPS);
                    float d1 = __log2f(s4.y + EPS) - __log2f(1.0f - s4.y + EPS);
                    float d2 = __log2f(s4.z + EPS) - __log2f(1.0f - s4.z + EPS);
                    float d3 = __log2f(s4.w + EPS) - __log2f(1.0f - s4.w + EPS);
                    int t0 = e / KS,       c0 = e - t0 * KS;
                    int t1 = (e+1) / KS,   c1 = (e+1) - t1 * KS;
                    int t2 = (e+2) / KS,   c2 = (e+2) - t2 * KS;
                    int t3 = (e+3) / KS,   c3 = (e+3) - t3 * KS;
                    sd[c0 * TPAD + t0] = d0;
                    sd[c1 * TPAD + t1] = d1;
                    sd[c2 * TPAD + t2] = d2;
                    sd[c3 * TPAD + t3] = d3;
                }
            }
            __syncthreads();

            // ---- Phase 2: FFMA micro-GEMM over this thread's segment ----
            if (act) {
                const float* sdk = sd + kk * TPAD;
                const float* mfg = mf + gq * TPAD;
                const int t0 = sidx * SEG;
                const int t1 = min(t0 + SEG, nt);
                for (int t = t0; t < t1; t += 4) {
                    float4 d4 = *(const float4*)(sdk + t);
                    float4 ma = *(const float4*)(mfg + t);
                    float4 mb = *(const float4*)(mfg + 5 * TPAD + t);
                    float4 mc = *(const float4*)(mfg + 10 * TPAD + t);
                    float4 md = *(const float4*)(mfg + 15 * TPAD + t);
                    a0 = fmaf(d4.x, ma.x, a0); a0 = fmaf(d4.y, ma.y, a0);
                    a0 = fmaf(d4.z, ma.z, a0); a0 = fmaf(d4.w, ma.w, a0);
                    a1 = fmaf(d4.x, mb.x, a1); a1 = fmaf(d4.y, mb.y, a1);
                    a1 = fmaf(d4.z, mb.z, a1); a1 = fmaf(d4.w, mb.w, a1);
                    a2 = fmaf(d4.x, mc.x, a2); a2 = fmaf(d4.y, mc.y, a2);
                    a2 = fmaf(d4.z, mc.z, a2); a2 = fmaf(d4.w, mc.w, a2);
                    a3 = fmaf(d4.x, md.x, a3); a3 = fmaf(d4.y, md.y, a3);
                    a3 = fmaf(d4.z, md.z, a3); a3 = fmaf(d4.w, md.w, a3);
                }
            }
            __syncthreads();
        }

        // ---- block reduce over 4 segments, then 4 atomics/output ----
        if (act) {
            float* sp = smem + j * 4;
            sp[0] = a0; sp[1] = a1; sp[2] = a2; sp[3] = a3;
        }
        __syncthreads();
        if (j < 105) {
            const int k2 = j / 5, g2 = j - k2 * 5;
            #pragma unroll
            for (int i = 0; i < 4; i++) {
                float s = smem[(0 * 105 + j) * 4 + i]
                        + smem[(1 * 105 + j) * 4 + i]
                        + smem[(2 * 105 + j) * 4 + i]
                        + smem[(3 * 105 + j) * 4 + i];
                atomicAdd(&g_D[k2 * GS + g2 + 5 * i], s);
            }
        }
    } else {
        // ================= generic path =================
        float* const sdg = smem;                       // sdg[t*K + k]
        unsigned* const smaskg = (unsigned*)(smem + K * T);

        int k0 = -1, k1 = -1;
        unsigned b0 = 0, b1 = 0;
        if (j < NPAIR)       { k0 = j / G;         b0 = 1u << (j % G); }
        if (j + 512 < NPAIR) { k1 = (j + 512) / G; b1 = 1u << ((j + 512) % G); }
        float acc0 = 0.0f, acc1 = 0.0f;

        for (int tile = blockIdx.x; tile < ntiles; tile += gridDim.x) {
            const int base = tile * T;
            const int nt = min(T, N - base);

            for (int t = j; t < nt; t += 512) {
                unsigned m = 0;
                for (int g = 0; g < G; g++)
                    if (gt[(size_t)g * N + base + t]) m |= 1u << g;
                smaskg[t] = m;
            }
            const int nelem = nt * K;
            const size_t off = (size_t)base * (size_t)K;
            for (int e = j; e < nelem; e += 512) {
                float s = seg[off + e];
                sdg[e] = __log2f(s + EPS) - __log2f(1.0f - s + EPS);
            }
            __syncthreads();

            if (k0 >= 0) {
                float a = 0.0f;
                for (int t = 0; t < nt; t++)
                    if (smaskg[t] & b0) a += sdg[t * K + k0];
                acc0 += a;
            }
            if (k1 >= 0) {
                float a = 0.0f;
                for (int t = 0; t < nt; t++)
                    if (smaskg[t] & b1) a += sdg[t * K + k1];
                acc1 += a;
            }
            __syncthreads();
        }
        if (k0 >= 0) atomicAdd(&g_D[j], acc0);
        if (k1 >= 0) atomicAdd(&g_D[j + 512], acc1);
    }

    // ---- last-block tail: argmax + output + reset ----
    __threadfence();
    if (j == 0) s_rank = atomicAdd(&g_cnt, 1u);
    __syncthreads();
    if (s_rank == (unsigned)(grid - 1)) {
        for (int p = j; p < NPAIR; p += 512) smem[p] = __ldcg(&g_D[p]);
        __syncthreads();
        for (int k = j; k < out_size; k += 512) {
            if (k < K) {
                float best = smem[k * G];
                int bi = 0;
                for (int g = 1; g < G; g++) {
                    float v = smem[k * G + g];
                    if (v > best) { best = v; bi = g; }  // first-max tie rule
                }
                out[k] = (float)bi;
            } else {
                out[k] = 0.0f;
            }
        }
        for (int p = j; p < NPAIR; p += 512) g_D[p] = 0.0f;  // reset for replay
        if (j == 0) g_cnt = 0;
    }
}

extern "C" void kernel_launch(void* const* d_in, const int* in_sizes, int n_in,
                              void* d_out, int out_size)
{
    // ---- identify inputs by size signature (ordering-invariant) ----
    int imax = 0;
    for (int i = 1; i < n_in; i++)
        if (in_sizes[i] > in_sizes[imax]) imax = i;
    int jmax = -1;
    for (int i = 0; i < n_in; i++)
        if (i != imax && in_sizes[i] == in_sizes[imax]) { jmax = i; break; }
    if (jmax < 0) {
        imax = 0;
        jmax = (n_in > 2) ? 2 : (n_in > 1 ? 1 : 0);
    }

    int N = 1;
    int gpn_idx = -1;
    for (int i = 0; i < n_in; i++) {
        if (i == imax || i == jmax) continue;
        if (in_sizes[i] > N) N = in_sizes[i];
        if (in_sizes[i] == 1) gpn_idx = i;
    }
    if (N < 1) N = 1;
    long long M = in_sizes[imax];
    int K = (int)(M / N);
    if (K < 1) K = 1;
    if (K > KS) K = KS;     // fixed-shape problem; smem sized for K<=21

    const int* gpn = (gpn_idx >= 0) ? (const int*)d_in[gpn_idx] : nullptr;

    // ---- tiling: T=288 (spec + generic both fit 47.9KB smem) ----
    int T = T_SPEC;                              // K*T + T <= SM_FLOATS for K<=21
    int ntiles = (N + T - 1) / T;
    int grid = ntiles < GRID_SPEC ? ntiles : GRID_SPEC;
    if (grid < 1) grid = 1;

    int nprobe = (int)(M < 32 ? M : 32);
    if (nprobe < 1) nprobe = 1;

    ms_kernel<<<grid, 512>>>(d_in[imax], d_in[jmax], gpn,
                             (float*)d_out, out_size,
                             N, K, T, grid, nprobe);
}

// round 13
// speedup vs baseline: 2.4106x; 1.0390x over previous
#include <cuda_runtime.h>

// MatchSegmentation, single fused kernel.
//   ce[k,g] = -( C_k + sum_n d[k,n]*gi[g,n] ) / N,  d = log(s+e)-log(1-s+e)
//   argmin_g ce == argmax_g D[k,g]  (positive scale ok -> log2, drop consts)
//
// R12 (resubmitted after infra timeout): occupancy round.
// launch_bounds(512,3) (42-reg cap -> 3 blocks/SM, 48 warps vs 32),
// T=256 (42.6KB smem, N/T exact), grid=444 (one wave).
// Phase 2 unchanged: FFMA micro-GEMM, 5x LDS.128 + 16 FFMA / 4 px.

#define EPS 1e-6f
#define KS 21
#define GS 20
#define NPS (KS * GS)              // 420
#define T_SPEC 256
#define TPAD 260                   // mult of 4; TPAD/4=65 odd -> bank spread
#define SEG 64                     // T_SPEC/4, multiple of 4 (16B alignment)
#define SD_FLOATS (KS * TPAD)      // 5460
#define MF_FLOATS (GS * TPAD)      // 5200
#define SM_FLOATS (SD_FLOATS + MF_FLOATS)  // 10660 floats = 42640 B
#define GRID_SPEC 444              // 3 blocks x 148 SMs, one wave
#define GMAX 32
#define NPMAX 1024

__device__ float g_D[NPMAX];       // zero-init at load; tail re-zeros
__device__ unsigned g_cnt = 0;

__global__ __launch_bounds__(512, 3) void ms_kernel(
    const void* __restrict__ Av, const void* __restrict__ Bv,
    const int* __restrict__ gpn, float* __restrict__ out,
    int out_size, int N, int K, int T, int grid, int nprobe)
{
    __shared__ float smem[SM_FLOATS];
    __shared__ int s_tmp[2];
    __shared__ int s_cfg[2];       // [0]=asel, [1]=G
    __shared__ unsigned s_rank;

    float* const sd = smem;                    // spec: sd[k*TPAD + t]
    float* const mf = smem + SD_FLOATS;        // spec: mf[g*TPAD + t]

    const int j = threadIdx.x;

    // ---- per-block probe: which big input is segmentation? ----
    if (j < 64) {
        int i = j & 31;
        int idx = (i < nprobe) ? i : 0;
        unsigned w = (j < 32) ? ((const unsigned*)Av)[idx]
                              : ((const unsigned*)Bv)[idx];
        unsigned bal = __ballot_sync(0xffffffffu, w > 1u);
        if ((j & 31) == 0) s_tmp[j >> 5] = __popc(bal);
    }
    __syncthreads();
    if (j == 0) {
        s_cfg[0] = (s_tmp[0] >= s_tmp[1]) ? 1 : 0;   // 1 -> A is seg
        int G = gpn ? *gpn : 20;
        if (G < 1 || G > 1000000) G = 20;
        if (G > GMAX) G = GMAX;
        if (G > K) G = K;
        if (G < 1) G = 1;
        s_cfg[1] = G;
    }
    __syncthreads();

    const int asel = s_cfg[0];
    const float* __restrict__ seg = asel ? (const float*)Av : (const float*)Bv;
    const int*   __restrict__ gt  = asel ? (const int*)Bv  : (const int*)Av;
    const int G = s_cfg[1];
    int NPAIR = K * G;
    if (NPAIR > NPMAX) NPAIR = NPMAX;

    const int ntiles = (N + T - 1) / T;
    const bool spec = (K == KS) && (G == GS) && ((N & 3) == 0) && (T == T_SPEC);

    if (spec) {
        // ================= specialized path: K=21, G=20 =================
        // thread (tid<420): s = tid/105; k = (tid%105)/5; gq = tid%5
        // owns outputs D[k][gq + 5i], i=0..3, over pixel segment s.
        const int sidx = j / 105;
        const int rem = j - sidx * 105;
        const int kk = rem / 5;
        const int gq = rem - kk * 5;
        const bool act = (j < NPS);
        float a0 = 0.f, a1 = 0.f, a2 = 0.f, a3 = 0.f;

        for (int tile = blockIdx.x; tile < ntiles; tile += gridDim.x) {
            const int base = tile * T_SPEC;
            const int nt = min(T_SPEC, N - base);   // multiple of 4

            // ---- Phase 1a: expand GT ints to float rows mf[g][t] ----
            for (int t = j; t < nt; t += 512) {
                const int* gp = gt + base + t;
                #pragma unroll
                for (int g = 0; g < GS; g++)
                    mf[g * TPAD + t] = (float)gp[(size_t)g * N];
            }

            // ---- Phase 1b: d = log2(s+e)-log2(1-s+e) into sd[k][t] ----
            {
                const float4* sv = (const float4*)(seg + (size_t)base * KS);
                const int n4 = (nt * KS) >> 2;
                for (int q = j; q < n4; q += 512) {
                    float4 s4 = sv[q];
                    const int e = 4 * q;
                    float d0 = __log2f(s4.x + EPS) - __log2f(1.0f - s4.x + EPS);
                    float d1 = __log2f(s4.y + EPS) - __log2f(1.0f - s4.y + EPS);
                    float d2 = __log2f(s4.z + EPS) - __log2f(1.0f - s4.z + EPS);
                    float d3 = __log2f(s4.w + EPS) - __log2f(1.0f - s4.w + EPS);
                    int t0 = e / KS,       c0 = e - t0 * KS;
                    int t1 = (e+1) / KS,   c1 = (e+1) - t1 * KS;
                    int t2 = (e+2) / KS,   c2 = (e+2) - t2 * KS;
                    int t3 = (e+3) / KS,   c3 = (e+3) - t3 * KS;
                    sd[c0 * TPAD + t0] = d0;
                    sd[c1 * TPAD + t1] = d1;
                    sd[c2 * TPAD + t2] = d2;
                    sd[c3 * TPAD + t3] = d3;
                }
            }
            __syncthreads();

            // ---- Phase 2: FFMA micro-GEMM over this thread's segment ----
            if (act) {
                const float* sdk = sd + kk * TPAD;
                const float* mfg = mf + gq * TPAD;
                const int t0 = sidx * SEG;
                const int t1 = min(t0 + SEG, nt);
                for (int t = t0; t < t1; t += 4) {
                    float4 d4 = *(const float4*)(sdk + t);
                    float4 ma = *(const float4*)(mfg + t);
                    float4 mb = *(const float4*)(mfg + 5 * TPAD + t);
                    float4 mc = *(const float4*)(mfg + 10 * TPAD + t);
                    float4 md = *(const float4*)(mfg + 15 * TPAD + t);
                    a0 = fmaf(d4.x, ma.x, a0); a0 = fmaf(d4.y, ma.y, a0);
                    a0 = fmaf(d4.z, ma.z, a0); a0 = fmaf(d4.w, ma.w, a0);
                    a1 = fmaf(d4.x, mb.x, a1); a1 = fmaf(d4.y, mb.y, a1);
                    a1 = fmaf(d4.z, mb.z, a1); a1 = fmaf(d4.w, mb.w, a1);
                    a2 = fmaf(d4.x, mc.x, a2); a2 = fmaf(d4.y, mc.y, a2);
                    a2 = fmaf(d4.z, mc.z, a2); a2 = fmaf(d4.w, mc.w, a2);
                    a3 = fmaf(d4.x, md.x, a3); a3 = fmaf(d4.y, md.y, a3);
                    a3 = fmaf(d4.z, md.z, a3); a3 = fmaf(d4.w, md.w, a3);
                }
            }
            __syncthreads();
        }

        // ---- block reduce over 4 segments, then 4 atomics/output ----
        if (act) {
            float* sp = smem + j * 4;
            sp[0] = a0; sp[1] = a1; sp[2] = a2; sp[3] = a3;
        }
        __syncthreads();
        if (j < 105) {
            const int k2 = j / 5, g2 = j - k2 * 5;
            #pragma unroll
            for (int i = 0; i < 4; i++) {
                float s = smem[(0 * 105 + j) * 4 + i]
                        + smem[(1 * 105 + j) * 4 + i]
                        + smem[(2 * 105 + j) * 4 + i]
                        + smem[(3 * 105 + j) * 4 + i];
                atomicAdd(&g_D[k2 * GS + g2 + 5 * i], s);
            }
        }
    } else {
        // ================= generic path =================
        float* const sdg = smem;                       // sdg[t*K + k]
        unsigned* const smaskg = (unsigned*)(smem + K * T);

        int k0 = -1, k1 = -1;
        unsigned b0 = 0, b1 = 0;
        if (j < NPAIR)       { k0 = j / G;         b0 = 1u << (j % G); }
        if (j + 512 < NPAIR) { k1 = (j + 512) / G; b1 = 1u << ((j + 512) % G); }
        float acc0 = 0.0f, acc1 = 0.0f;

        for (int tile = blockIdx.x; tile < ntiles; tile += gridDim.x) {
            const int base = tile * T;
            const int nt = min(T, N - base);

            for (int t = j; t < nt; t += 512) {
                unsigned m = 0;
                for (int g = 0; g < G; g++)
                    if (gt[(size_t)g * N + base + t]) m |= 1u << g;
                smaskg[t] = m;
            }
            const int nelem = nt * K;
            const size_t off = (size_t)base * (size_t)K;
            for (int e = j; e < nelem; e += 512) {
                float s = seg[off + e];
                sdg[e] = __log2f(s + EPS) - __log2f(1.0f - s + EPS);
            }
            __syncthreads();

            if (k0 >= 0) {
                float a = 0.0f;
                for (int t = 0; t < nt; t++)
                    if (smaskg[t] & b0) a += sdg[t * K + k0];
                acc0 += a;
            }
            if (k1 >= 0) {
                float a = 0.0f;
                for (int t = 0; t < nt; t++)
                    if (smaskg[t] & b1) a += sdg[t * K + k1];
                acc1 += a;
            }
            __syncthreads();
        }
        if (k0 >= 0) atomicAdd(&g_D[j], acc0);
        if (k1 >= 0) atomicAdd(&g_D[j + 512], acc1);
    }

    // ---- last-block tail: argmax + output + reset ----
    __threadfence();
    if (j == 0) s_rank = atomicAdd(&g_cnt, 1u);
    __syncthreads();
    if (s_rank == (unsigned)(grid - 1)) {
        for (int p = j; p < NPAIR; p += 512) smem[p] = __ldcg(&g_D[p]);
        __syncthreads();
        for (int k = j; k < out_size; k += 512) {
            if (k < K) {
                float best = smem[k * G];
                int bi = 0;
                for (int g = 1; g < G; g++) {
                    float v = smem[k * G + g];
                    if (v > best) { best = v; bi = g; }  // first-max tie rule
                }
                out[k] = (float)bi;
            } else {
                out[k] = 0.0f;
            }
        }
        for (int p = j; p < NPAIR; p += 512) g_D[p] = 0.0f;  // reset for replay
        if (j == 0) g_cnt = 0;
    }
}

extern "C" void kernel_launch(void* const* d_in, const int* in_sizes, int n_in,
                              void* d_out, int out_size)
{
    // ---- identify inputs by size signature (ordering-invariant) ----
    int imax = 0;
    for (int i = 1; i < n_in; i++)
        if (in_sizes[i] > in_sizes[imax]) imax = i;
    int jmax = -1;
    for (int i = 0; i < n_in; i++)
        if (i != imax && in_sizes[i] == in_sizes[imax]) { jmax = i; break; }
    if (jmax < 0) {
        imax = 0;
        jmax = (n_in > 2) ? 2 : (n_in > 1 ? 1 : 0);
    }

    int N = 1;
    int gpn_idx = -1;
    for (int i = 0; i < n_in; i++) {
        if (i == imax || i == jmax) continue;
        if (in_sizes[i] > N) N = in_sizes[i];
        if (in_sizes[i] == 1) gpn_idx = i;
    }
    if (N < 1) N = 1;
    long long M = in_sizes[imax];
    int K = (int)(M / N);
    if (K < 1) K = 1;
    if (K > KS) K = KS;     // fixed-shape problem; smem sized for K<=21

    const int* gpn = (gpn_idx >= 0) ? (const int*)d_in[gpn_idx] : nullptr;

    // ---- tiling: T=256 (spec + generic both fit 42.6KB smem) ----
    int T = T_SPEC;                              // (K+1)*T <= SM_FLOATS for K<=21
    int ntiles = (N + T - 1) / T;
    int grid = ntiles < GRID_SPEC ? ntiles : GRID_SPEC;
    if (grid < 1) grid = 1;

    int nprobe = (int)(M < 32 ? M : 32);
    if (nprobe < 1) nprobe = 1;

    ms_kernel<<<grid, 512>>>(d_in[imax], d_in[jmax], gpn,
                             (float*)d_out, out_size,
                             N, K, T, grid, nprobe);
}

// round 16
// speedup vs baseline: 2.4903x; 1.0331x over previous
#include <cuda_runtime.h>

// MatchSegmentation, single fused kernel.
//   ce[k,g] = -( C_k + sum_n d[k,n]*gi[g,n] ) / N,  d = log(s+e)-log(1-s+e)
//   argmin_g ce == argmax_g D[k,g]  (positive scale ok -> log2, drop consts)
//
// R14 (third submission; repeated infra timeouts): warp-specialized
// pipeline. Producers (tid>=352, 5 warps) build tile s+1 (LDG gt->float
// rows, log2 seg -> transposed sd) into buf[s&1] while consumers (tid<336
// = 84 (k,c) combos x 4 segments, 5 g's each) run the FFMA micro-GEMM on
// tile s from buf[(s^1)&1]. One __syncthreads per step. T=128
// double-buffered (43.3KB static smem), launch_bounds(512,3).

#define EPS 1e-6f
#define KS 21
#define GS 20
#define NPS (KS * GS)              // 420
#define T_SPEC 128
#define TPAD 132                   // mult of 4; 132 mod 32 = 4 -> bank spread
#define SEG 32                     // T_SPEC/4
#define SDF (KS * TPAD)            // 2772
#define MFF (GS * TPAD)            // 2640
#define BUF (SDF + MFF)            // 5412
#define SM_FLOATS (2 * BUF)        // 10824 floats = 43296 B
#define GRID_SPEC 444
#define GMAX 32
#define NPMAX 1024
#define NCONS 336
#define PSTART 352
#define NPROD 160

__device__ float g_D[NPMAX];       // zero-init at load; tail re-zeros
__device__ unsigned g_cnt = 0;

__device__ __forceinline__ void ms_proc_quad(float* sdw, int q, float4 s4)
{
    const int e = 4 * q;
    float d0 = __log2f(s4.x + EPS) - __log2f(1.0f - s4.x + EPS);
    float d1 = __log2f(s4.y + EPS) - __log2f(1.0f - s4.y + EPS);
    float d2 = __log2f(s4.z + EPS) - __log2f(1.0f - s4.z + EPS);
    float d3 = __log2f(s4.w + EPS) - __log2f(1.0f - s4.w + EPS);
    int t0 = e / KS,     c0 = e - t0 * KS;
    int t1 = (e+1) / KS, c1 = (e+1) - t1 * KS;
    int t2 = (e+2) / KS, c2 = (e+2) - t2 * KS;
    int t3 = (e+3) / KS, c3 = (e+3) - t3 * KS;
    sdw[c0 * TPAD + t0] = d0;
    sdw[c1 * TPAD + t1] = d1;
    sdw[c2 * TPAD + t2] = d2;
    sdw[c3 * TPAD + t3] = d3;
}

__global__ __launch_bounds__(512, 3) void ms_kernel(
    const void* __restrict__ Av, const void* __restrict__ Bv,
    const int* __restrict__ gpn, float* __restrict__ out,
    int out_size, int N, int K, int T, int grid, int nprobe)
{
    __shared__ float smem[SM_FLOATS];
    __shared__ int s_tmp[2];
    __shared__ int s_cfg[2];       // [0]=asel, [1]=G
    __shared__ unsigned s_rank;

    const int j = threadIdx.x;

    // ---- per-block probe: which big input is segmentation? ----
    if (j < 64) {
        int i = j & 31;
        int idx = (i < nprobe) ? i : 0;
        unsigned w = (j < 32) ? ((const unsigned*)Av)[idx]
                              : ((const unsigned*)Bv)[idx];
        unsigned bal = __ballot_sync(0xffffffffu, w > 1u);
        if ((j & 31) == 0) s_tmp[j >> 5] = __popc(bal);
    }
    __syncthreads();
    if (j == 0) {
        s_cfg[0] = (s_tmp[0] >= s_tmp[1]) ? 1 : 0;   // 1 -> A is seg
        int G = gpn ? *gpn : 20;
        if (G < 1 || G > 1000000) G = 20;
        if (G > GMAX) G = GMAX;
        if (G > K) G = K;
        if (G < 1) G = 1;
        s_cfg[1] = G;
    }
    __syncthreads();

    const int asel = s_cfg[0];
    const float* __restrict__ seg = asel ? (const float*)Av : (const float*)Bv;
    const int*   __restrict__ gt  = asel ? (const int*)Bv  : (const int*)Av;
    const int G = s_cfg[1];
    int NPAIR = K * G;
    if (NPAIR > NPMAX) NPAIR = NPMAX;

    const int ntiles = (N + T - 1) / T;
    const bool spec = (K == KS) && (G == GS) && ((N & 3) == 0) && (T == T_SPEC);

    if (spec) {
        // ============ specialized pipelined path: K=21, G=20 ============
        const int sidx = j / 84;              // 0..3 for consumers
        const int combo = j - sidx * 84;      // 0..83
        const int kk = combo >> 2;            // k = 0..20
        const int cc = combo & 3;             // g base: g = cc + 4i
        const bool is_cons = (j < NCONS);
        const bool is_prod = (j >= PSTART);
        const int p = j - PSTART;             // producer lane 0..159
        float a0 = 0.f, a1 = 0.f, a2 = 0.f, a3 = 0.f, a4 = 0.f;

        for (int s = 0; ; s++) {
            const long tp = (long)blockIdx.x + (long)s * gridDim.x;
            const long tc = tp - gridDim.x;
            const bool dp = (tp < (long)ntiles);
            const bool dc = (s >= 1) && (tc < (long)ntiles);
            if (!dp && !dc) break;

            float* const sdw = smem + ((s & 1) ? BUF : 0);
            float* const mfw = sdw + SDF;
            const float* const sdr = smem + ((s & 1) ? 0 : BUF);
            const float* const mfr = sdr + SDF;

            if (is_prod && dp) {
                const int base = (int)tp * T_SPEC;
                const int nt = min(T_SPEC, N - base);

                // Phase 1a: gt ints -> float rows mf[g][t] (MLP 20)
                if (p < nt) {
                    const int* gp = gt + base + p;
                    #pragma unroll
                    for (int g = 0; g < GS; g++)
                        mfw[g * TPAD + p] = (float)gp[(size_t)g * N];
                }

                // Phase 1b: log2 transform, transposed store (batched LDG)
                const int n4 = (nt * KS) >> 2;
                const float4* sv = (const float4*)(seg + (size_t)base * KS);
                const bool h0 = p < n4, h1 = p + NPROD < n4,
                           h2 = p + 2*NPROD < n4, h3 = p + 3*NPROD < n4,
                           h4 = p + 4*NPROD < n4;
                float4 v0, v1, v2, v3, v4;
                if (h0) v0 = sv[p];
                if (h1) v1 = sv[p + NPROD];
                if (h2) v2 = sv[p + 2*NPROD];
                if (h3) v3 = sv[p + 3*NPROD];
                if (h4) v4 = sv[p + 4*NPROD];
                if (h0) ms_proc_quad(sdw, p, v0);
                if (h1) ms_proc_quad(sdw, p + NPROD, v1);
                if (h2) ms_proc_quad(sdw, p + 2*NPROD, v2);
                if (h3) ms_proc_quad(sdw, p + 3*NPROD, v3);
                if (h4) ms_proc_quad(sdw, p + 4*NPROD, v4);
            }

            if (is_cons && dc) {
                const int base = (int)tc * T_SPEC;
                const int nt = min(T_SPEC, N - base);
                const float* sdk = sdr + kk * TPAD;
                const float* mfg = mfr + cc * TPAD;
                const int t0s = sidx * SEG;
                const int t1s = min(t0s + SEG, nt);
                for (int t = t0s; t < t1s; t += 4) {
                    float4 d4 = *(const float4*)(sdk + t);
                    float4 m0 = *(const float4*)(mfg + t);
                    a0 = fmaf(d4.x, m0.x, a0); a0 = fmaf(d4.y, m0.y, a0);
                    a0 = fmaf(d4.z, m0.z, a0); a0 = fmaf(d4.w, m0.w, a0);
                    float4 m1 = *(const float4*)(mfg + 4 * TPAD + t);
                    a1 = fmaf(d4.x, m1.x, a1); a1 = fmaf(d4.y, m1.y, a1);
                    a1 = fmaf(d4.z, m1.z, a1); a1 = fmaf(d4.w, m1.w, a1);
                    float4 m2 = *(const float4*)(mfg + 8 * TPAD + t);
                    a2 = fmaf(d4.x, m2.x, a2); a2 = fmaf(d4.y, m2.y, a2);
                    a2 = fmaf(d4.z, m2.z, a2); a2 = fmaf(d4.w, m2.w, a2);
                    float4 m3 = *(const float4*)(mfg + 12 * TPAD + t);
                    a3 = fmaf(d4.x, m3.x, a3); a3 = fmaf(d4.y, m3.y, a3);
                    a3 = fmaf(d4.z, m3.z, a3); a3 = fmaf(d4.w, m3.w, a3);
                    float4 m4 = *(const float4*)(mfg + 16 * TPAD + t);
                    a4 = fmaf(d4.x, m4.x, a4); a4 = fmaf(d4.y, m4.y, a4);
                    a4 = fmaf(d4.z, m4.z, a4); a4 = fmaf(d4.w, m4.w, a4);
                }
            }
            __syncthreads();
        }

        // ---- block reduce: 336 threads x 5 accs -> 84 x 5 atomics ----
        if (is_cons) {
            float* sp = smem + j * 5;
            sp[0] = a0; sp[1] = a1; sp[2] = a2; sp[3] = a3; sp[4] = a4;
        }
        __syncthreads();
        if (j < 84) {
            const int kk2 = j >> 2, cc2 = j & 3;
            #pragma unroll
            for (int i = 0; i < 5; i++) {
                float sum = smem[j * 5 + i]
                          + smem[(84 + j) * 5 + i]
                          + smem[(168 + j) * 5 + i]
                          + smem[(252 + j) * 5 + i];
                atomicAdd(&g_D[kk2 * GS + cc2 + 4 * i], sum);
            }
        }
    } else {
        // ================= generic path =================
        float* const sdg = smem;                       // sdg[t*K + k]
        unsigned* const smaskg = (unsigned*)(smem + K * T);

        int k0 = -1, k1 = -1;
        unsigned b0 = 0, b1 = 0;
        if (j < NPAIR)       { k0 = j / G;         b0 = 1u << (j % G); }
        if (j + 512 < NPAIR) { k1 = (j + 512) / G; b1 = 1u << ((j + 512) % G); }
        float acc0 = 0.0f, acc1 = 0.0f;

        for (int tile = blockIdx.x; tile < ntiles; tile += gridDim.x) {
            const int base = tile * T;
            const int nt = min(T, N - base);

            for (int t = j; t < nt; t += 512) {
                unsigned m = 0;
                for (int g = 0; g < G; g++)
                    if (gt[(size_t)g * N + base + t]) m |= 1u << g;
                smaskg[t] = m;
            }
            const int nelem = nt * K;
            const size_t off = (size_t)base * (size_t)K;
            for (int e = j; e < nelem; e += 512) {
                float s = seg[off + e];
                sdg[e] = __log2f(s + EPS) - __log2f(1.0f - s + EPS);
            }
            __syncthreads();

            if (k0 >= 0) {
                float a = 0.0f;
                for (int t = 0; t < nt; t++)
                    if (smaskg[t] & b0) a += sdg[t * K + k0];
                acc0 += a;
            }
            if (k1 >= 0) {
                float a = 0.0f;
                for (int t = 0; t < nt; t++)
                    if (smaskg[t] & b1) a += sdg[t * K + k1];
                acc1 += a;
            }
            __syncthreads();
        }
        if (k0 >= 0) atomicAdd(&g_D[j], acc0);
        if (k1 >= 0) atomicAdd(&g_D[j + 512], acc1);
    }

    // ---- last-block tail: argmax + output + reset ----
    __threadfence();
    if (j == 0) s_rank = atomicAdd(&g_cnt, 1u);
    __syncthreads();
    if (s_rank == (unsigned)(grid - 1)) {
        for (int pq = j; pq < NPAIR; pq += 512) smem[pq] = __ldcg(&g_D[pq]);
        __syncthreads();
        for (int k = j; k < out_size; k += 512) {
            if (k < K) {
                float best = smem[k * G];
                int bi = 0;
                for (int g = 1; g < G; g++) {
                    float v = smem[k * G + g];
                    if (v > best) { best = v; bi = g; }  // first-max tie rule
                }
                out[k] = (float)bi;
            } else {
                out[k] = 0.0f;
            }
        }
        for (int pq = j; pq < NPAIR; pq += 512) g_D[pq] = 0.0f;  // reset
        if (j == 0) g_cnt = 0;
    }
}

extern "C" void kernel_launch(void* const* d_in, const int* in_sizes, int n_in,
                              void* d_out, int out_size)
{
    // ---- identify inputs by size signature (ordering-invariant) ----
    int imax = 0;
    for (int i = 1; i < n_in; i++)
        if (in_sizes[i] > in_sizes[imax]) imax = i;
    int jmax = -1;
    for (int i = 0; i < n_in; i++)
        if (i != imax && in_sizes[i] == in_sizes[imax]) { jmax = i; break; }
    if (jmax < 0) {
        imax = 0;
        jmax = (n_in > 2) ? 2 : (n_in > 1 ? 1 : 0);
    }

    int N = 1;
    int gpn_idx = -1;
    for (int i = 0; i < n_in; i++) {
        if (i == imax || i == jmax) continue;
        if (in_sizes[i] > N) N = in_sizes[i];
        if (in_sizes[i] == 1) gpn_idx = i;
    }
    if (N < 1) N = 1;
    long long M = in_sizes[imax];
    int K = (int)(M / N);
    if (K < 1) K = 1;
    if (K > KS) K = KS;     // fixed-shape problem; smem sized for K<=21

    const int* gpn = (gpn_idx >= 0) ? (const int*)d_in[gpn_idx] : nullptr;

    // ---- tiling: T=128 (spec pipeline; generic also fits) ----
    int T = T_SPEC;
    int ntiles = (N + T - 1) / T;
    int grid = ntiles < GRID_SPEC ? ntiles : GRID_SPEC;
    if (grid < 1) grid = 1;

    int nprobe = (int)(M < 32 ? M : 32);
    if (nprobe < 1) nprobe = 1;

    ms_kernel<<<grid, 512>>>(d_in[imax], d_in[jmax], gpn,
                             (float*)d_out, out_size,
                             N, K, T, grid, nprobe);
}

// round 17
// speedup vs baseline: 2.6759x; 1.0745x over previous
#include <cuda_runtime.h>

// MatchSegmentation, single fused kernel.
//   ce[k,g] = -( C_k + sum_n d[k,n]*gi[g,n] ) / N,  d = log(s+e)-log(1-s+e)
//   argmin_g ce == argmax_g D[k,g]  (positive scale ok -> log2, drop consts)
//
// R17: consumer math in packed f32x2 (sm_103a FFMA2 via PTX fma.rn.f32x2):
// 10 FFMA2 + 6 LDS.128 per 4 px (was 20 FFMA), fully unrolled 8-iter inner
// loop (N%T==0 in spec guard -> compile-time trip count). Pipeline,
// producers, tail identical to R16 (warp-specialized double-buffered T=128).

#define EPS 1e-6f
#define KS 21
#define GS 20
#define NPS (KS * GS)              // 420
#define T_SPEC 128
#define TPAD 132                   // mult of 4; 132 mod 32 = 4 -> bank spread
#define SEG 32                     // T_SPEC/4
#define SDF (KS * TPAD)            // 2772
#define MFF (GS * TPAD)            // 2640
#define BUF (SDF + MFF)            // 5412
#define SM_FLOATS (2 * BUF)        // 10824 floats = 43296 B
#define GRID_SPEC 444
#define GMAX 32
#define NPMAX 1024
#define NCONS 336
#define PSTART 352
#define NPROD 160

// packed f32x2 fused multiply-add: acc.lo += a.lo*b.lo; acc.hi += a.hi*b.hi
#define FMA2(acc, a, b) \
    asm("fma.rn.f32x2 %0, %1, %2, %0;" : "+l"(acc) : "l"(a), "l"(b))

__device__ float g_D[NPMAX];       // zero-init at load; tail re-zeros
__device__ unsigned g_cnt = 0;

__device__ __forceinline__ void ms_proc_quad(float* sdw, int q, float4 s4)
{
    const int e = 4 * q;
    float d0 = __log2f(s4.x + EPS) - __log2f(1.0f - s4.x + EPS);
    float d1 = __log2f(s4.y + EPS) - __log2f(1.0f - s4.y + EPS);
    float d2 = __log2f(s4.z + EPS) - __log2f(1.0f - s4.z + EPS);
    float d3 = __log2f(s4.w + EPS) - __log2f(1.0f - s4.w + EPS);
    int t0 = e / KS,     c0 = e - t0 * KS;
    int t1 = (e+1) / KS, c1 = (e+1) - t1 * KS;
    int t2 = (e+2) / KS, c2 = (e+2) - t2 * KS;
    int t3 = (e+3) / KS, c3 = (e+3) - t3 * KS;
    sdw[c0 * TPAD + t0] = d0;
    sdw[c1 * TPAD + t1] = d1;
    sdw[c2 * TPAD + t2] = d2;
    sdw[c3 * TPAD + t3] = d3;
}

__global__ __launch_bounds__(512, 3) void ms_kernel(
    const void* __restrict__ Av, const void* __restrict__ Bv,
    const int* __restrict__ gpn, float* __restrict__ out,
    int out_size, int N, int K, int T, int grid, int nprobe)
{
    __shared__ float smem[SM_FLOATS];
    __shared__ int s_tmp[2];
    __shared__ int s_cfg[2];       // [0]=asel, [1]=G
    __shared__ unsigned s_rank;

    const int j = threadIdx.x;

    // ---- per-block probe: which big input is segmentation? ----
    if (j < 64) {
        int i = j & 31;
        int idx = (i < nprobe) ? i : 0;
        unsigned w = (j < 32) ? ((const unsigned*)Av)[idx]
                              : ((const unsigned*)Bv)[idx];
        unsigned bal = __ballot_sync(0xffffffffu, w > 1u);
        if ((j & 31) == 0) s_tmp[j >> 5] = __popc(bal);
    }
    __syncthreads();
    if (j == 0) {
        s_cfg[0] = (s_tmp[0] >= s_tmp[1]) ? 1 : 0;   // 1 -> A is seg
        int G = gpn ? *gpn : 20;
        if (G < 1 || G > 1000000) G = 20;
        if (G > GMAX) G = GMAX;
        if (G > K) G = K;
        if (G < 1) G = 1;
        s_cfg[1] = G;
    }
    __syncthreads();

    const int asel = s_cfg[0];
    const float* __restrict__ seg = asel ? (const float*)Av : (const float*)Bv;
    const int*   __restrict__ gt  = asel ? (const int*)Bv  : (const int*)Av;
    const int G = s_cfg[1];
    int NPAIR = K * G;
    if (NPAIR > NPMAX) NPAIR = NPMAX;

    const int ntiles = (N + T - 1) / T;
    const bool spec = (K == KS) && (G == GS) && (T == T_SPEC) &&
                      ((N % T_SPEC) == 0);

    if (spec) {
        // ============ specialized pipelined path: K=21, G=20 ============
        const int sidx = j / 84;              // 0..3 for consumers
        const int combo = j - sidx * 84;      // 0..83
        const int kk = combo >> 2;            // k = 0..20
        const int cc = combo & 3;             // g base: g = cc + 4i
        const bool is_cons = (j < NCONS);
        const bool is_prod = (j >= PSTART);
        const int p = j - PSTART;             // producer lane 0..159
        unsigned long long a0 = 0ull, a1 = 0ull, a2 = 0ull,
                           a3 = 0ull, a4 = 0ull;   // packed f32x2 accums

        for (int s = 0; ; s++) {
            const long tp = (long)blockIdx.x + (long)s * gridDim.x;
            const long tc = tp - gridDim.x;
            const bool dp = (tp < (long)ntiles);
            const bool dc = (s >= 1) && (tc < (long)ntiles);
            if (!dp && !dc) break;

            float* const sdw = smem + ((s & 1) ? BUF : 0);
            float* const mfw = sdw + SDF;
            const float* const sdr = smem + ((s & 1) ? 0 : BUF);
            const float* const mfr = sdr + SDF;

            if (is_prod && dp) {
                const int base = (int)tp * T_SPEC;

                // Phase 1a: gt ints -> float rows mf[g][t] (MLP 20)
                if (p < T_SPEC) {
                    const int* gp = gt + base + p;
                    #pragma unroll
                    for (int g = 0; g < GS; g++)
                        mfw[g * TPAD + p] = (float)gp[(size_t)g * N];
                }

                // Phase 1b: log2 transform, transposed store (batched LDG)
                const int n4 = (T_SPEC * KS) >> 2;   // 672
                const float4* sv = (const float4*)(seg + (size_t)base * KS);
                const bool h0 = p < n4, h1 = p + NPROD < n4,
                           h2 = p + 2*NPROD < n4, h3 = p + 3*NPROD < n4,
                           h4 = p + 4*NPROD < n4;
                float4 v0, v1, v2, v3, v4;
                if (h0) v0 = sv[p];
                if (h1) v1 = sv[p + NPROD];
                if (h2) v2 = sv[p + 2*NPROD];
                if (h3) v3 = sv[p + 3*NPROD];
                if (h4) v4 = sv[p + 4*NPROD];
                if (h0) ms_proc_quad(sdw, p, v0);
                if (h1) ms_proc_quad(sdw, p + NPROD, v1);
                if (h2) ms_proc_quad(sdw, p + 2*NPROD, v2);
                if (h3) ms_proc_quad(sdw, p + 3*NPROD, v3);
                if (h4) ms_proc_quad(sdw, p + 4*NPROD, v4);
            }

            if (is_cons && dc) {
                const float* sdk = sdr + kk * TPAD;
                const float* mfg = mfr + cc * TPAD;
                const int t0s = sidx * SEG;
                #pragma unroll
                for (int it = 0; it < SEG / 4; it++) {
                    const int t = t0s + 4 * it;
                    ulonglong2 d2 = *(const ulonglong2*)(sdk + t);
                    ulonglong2 m;
                    m = *(const ulonglong2*)(mfg + t);
                    FMA2(a0, d2.x, m.x); FMA2(a0, d2.y, m.y);
                    m = *(const ulonglong2*)(mfg + 4 * TPAD + t);
                    FMA2(a1, d2.x, m.x); FMA2(a1, d2.y, m.y);
                    m = *(const ulonglong2*)(mfg + 8 * TPAD + t);
                    FMA2(a2, d2.x, m.x); FMA2(a2, d2.y, m.y);
                    m = *(const ulonglong2*)(mfg + 12 * TPAD + t);
                    FMA2(a3, d2.x, m.x); FMA2(a3, d2.y, m.y);
                    m = *(const ulonglong2*)(mfg + 16 * TPAD + t);
                    FMA2(a4, d2.x, m.x); FMA2(a4, d2.y, m.y);
                }
            }
            __syncthreads();
        }

        // ---- block reduce: 336 threads x 5 accs -> 84 x 5 atomics ----
        if (is_cons) {
            float* sp = smem + j * 5;
            sp[0] = __uint_as_float((unsigned)a0)
                  + __uint_as_float((unsigned)(a0 >> 32));
            sp[1] = __uint_as_float((unsigned)a1)
                  + __uint_as_float((unsigned)(a1 >> 32));
            sp[2] = __uint_as_float((unsigned)a2)
                  + __uint_as_float((unsigned)(a2 >> 32));
            sp[3] = __uint_as_float((unsigned)a3)
                  + __uint_as_float((unsigned)(a3 >> 32));
            sp[4] = __uint_as_float((unsigned)a4)
                  + __uint_as_float((unsigned)(a4 >> 32));
        }
        __syncthreads();
        if (j < 84) {
            const int kk2 = j >> 2, cc2 = j & 3;
            #pragma unroll
            for (int i = 0; i < 5; i++) {
                float sum = smem[j * 5 + i]
                          + smem[(84 + j) * 5 + i]
                          + smem[(168 + j) * 5 + i]
                          + smem[(252 + j) * 5 + i];
                atomicAdd(&g_D[kk2 * GS + cc2 + 4 * i], sum);
            }
        }
    } else {
        // ================= generic path =================
        float* const sdg = smem;                       // sdg[t*K + k]
        unsigned* const smaskg = (unsigned*)(smem + K * T);

        int k0 = -1, k1 = -1;
        unsigned b0 = 0, b1 = 0;
        if (j < NPAIR)       { k0 = j / G;         b0 = 1u << (j % G); }
        if (j + 512 < NPAIR) { k1 = (j + 512) / G; b1 = 1u << ((j + 512) % G); }
        float acc0 = 0.0f, acc1 = 0.0f;

        for (int tile = blockIdx.x; tile < ntiles; tile += gridDim.x) {
            const int base = tile * T;
            const int nt = min(T, N - base);

            for (int t = j; t < nt; t += 512) {
                unsigned m = 0;
                for (int g = 0; g < G; g++)
                    if (gt[(size_t)g * N + base + t]) m |= 1u << g;
                smaskg[t] = m;
            }
            const int nelem = nt * K;
            const size_t off = (size_t)base * (size_t)K;
            for (int e = j; e < nelem; e += 512) {
                float s = seg[off + e];
                sdg[e] = __log2f(s + EPS) - __log2f(1.0f - s + EPS);
            }
            __syncthreads();

            if (k0 >= 0) {
                float a = 0.0f;
                for (int t = 0; t < nt; t++)
                    if (smaskg[t] & b0) a += sdg[t * K + k0];
                acc0 += a;
            }
            if (k1 >= 0) {
                float a = 0.0f;
                for (int t = 0; t < nt; t++)
                    if (smaskg[t] & b1) a += sdg[t * K + k1];
                acc1 += a;
            }
            __syncthreads();
        }
        if (k0 >= 0) atomicAdd(&g_D[j], acc0);
        if (k1 >= 0) atomicAdd(&g_D[j + 512], acc1);
    }

    // ---- last-block tail: argmax + output + reset ----
    __threadfence();
    if (j == 0) s_rank = atomicAdd(&g_cnt, 1u);
    __syncthreads();
    if (s_rank == (unsigned)(grid - 1)) {
        for (int pq = j; pq < NPAIR; pq += 512) smem[pq] = __ldcg(&g_D[pq]);
        __syncthreads();
        for (int k = j; k < out_size; k += 512) {
            if (k < K) {
                float best = smem[k * G];
                int bi = 0;
                for (int g = 1; g < G; g++) {
                    float v = smem[k * G + g];
                    if (v > best) { best = v; bi = g; }  // first-max tie rule
                }
                out[k] = (float)bi;
            } else {
                out[k] = 0.0f;
            }
        }
        for (int pq = j; pq < NPAIR; pq += 512) g_D[pq] = 0.0f;  // reset
        if (j == 0) g_cnt = 0;
    }
}

extern "C" void kernel_launch(void* const* d_in, const int* in_sizes, int n_in,
                              void* d_out, int out_size)
{
    // ---- identify inputs by size signature (ordering-invariant) ----
    int imax = 0;
    for (int i = 1; i < n_in; i++)
        if (in_sizes[i] > in_sizes[imax]) imax = i;
    int jmax = -1;
    for (int i = 0; i < n_in; i++)
        if (i != imax && in_sizes[i] == in_sizes[imax]) { jmax = i; break; }
    if (jmax < 0) {
        imax = 0;
        jmax = (n_in > 2) ? 2 : (n_in > 1 ? 1 : 0);
    }

    int N = 1;
    int gpn_idx = -1;
    for (int i = 0; i < n_in; i++) {
        if (i == imax || i == jmax) continue;
        if (in_sizes[i] > N) N = in_sizes[i];
        if (in_sizes[i] == 1) gpn_idx = i;
    }
    if (N < 1) N = 1;
    long long M = in_sizes[imax];
    int K = (int)(M / N);
    if (K < 1) K = 1;
    if (K > KS) K = KS;     // fixed-shape problem; smem sized for K<=21

    const int* gpn = (gpn_idx >= 0) ? (const int*)d_in[gpn_idx] : nullptr;

    // ---- tiling: T=128 (spec pipeline; generic also fits) ----
    int T = T_SPEC;
    int ntiles = (N + T - 1) / T;
    int grid = ntiles < GRID_SPEC ? ntiles : GRID_SPEC;
    if (grid < 1) grid = 1;

    int nprobe = (int)(M < 32 ? M : 32);
    if (nprobe < 1) nprobe = 1;

    ms_kernel<<<grid, 512>>>(d_in[imax], d_in[jmax], gpn,
                             (float*)d_out, out_size,
                             N, K, T, grid, nprobe);
}